// round 12
// baseline (speedup 1.0000x reference)
#include <cuda_runtime.h>
#include <cstdint>

#define FULL 0xffffffffu
typedef unsigned long long u64;

constexpr int Bn = 128;      // batch
constexpr int Sn = 512;      // seq len
constexpr int Dk = 1024;     // feature dim
constexpr int Ln = 50;       // real labels
constexpr int NL = 52;       // labels + START + END
constexpr int STARTL = 50;
constexpr int ENDL = 51;
constexpr float NEGV = -100.0f;
constexpr float LOG2E = 1.4426950408889634f;
constexpr float LN2   = 0.6931471805599453f;

// ---- fused kernel config ----
constexpr int KCH  = 32;            // k per chunk
constexpr int NCHK = Dk / KCH;      // 32 chunks
constexpr int KP   = 36;            // padded k stride (floats)
constexpr int AS1  = 128 * KP;      // floats per A stage (4608)
constexpr int BS1  = 64 * KP;       // floats per B stage (2304)
constexpr int SMEM_BYTES = (3 * AS1 + 3 * BS1) * 4;   // 82944 (3-stage)
constexpr int GEMM_CTAS = 168;
constexpr int NTILES = 512;         // 4 s-tiles x 128 batches, tau = tr*128 + b

// Scratch (device globals — no allocation allowed)
__device__ float g_logits[(size_t)Bn * Sn * Ln];   // 13.1 MB
__device__ float g_partial[Bn];
__device__ int   g_flags[NTILES];
__device__ int   g_ctr;
__device__ int   g_done;

// ---------------- PTX helpers ----------------
__device__ __forceinline__ unsigned smem_u32(const void* p) {
    unsigned a;
    asm("{ .reg .u64 t; cvta.to.shared.u64 t, %1; cvt.u32.u64 %0, t; }"
        : "=r"(a) : "l"(p));
    return a;
}
__device__ __forceinline__ void cp16(unsigned dst, const void* src) {
    asm volatile("cp.async.cg.shared.global [%0], [%1], 16;"
                 :: "r"(dst), "l"(src) : "memory");
}
__device__ __forceinline__ void cp_commit() {
    asm volatile("cp.async.commit_group;" ::: "memory");
}
template <int N>
__device__ __forceinline__ void cp_wait() {
    asm volatile("cp.async.wait_group %0;" :: "n"(N) : "memory");
}
__device__ __forceinline__ void mma_tf32(float* c, const unsigned* a,
                                         unsigned b0, unsigned b1) {
    asm volatile(
        "mma.sync.aligned.m16n8k8.row.col.f32.tf32.tf32.f32 "
        "{%0,%1,%2,%3}, {%4,%5,%6,%7}, {%8,%9}, {%0,%1,%2,%3};"
        : "+f"(c[0]), "+f"(c[1]), "+f"(c[2]), "+f"(c[3])
        : "r"(a[0]), "r"(a[1]), "r"(a[2]), "r"(a[3]), "r"(b0), "r"(b1));
}
__device__ __forceinline__ u64 packlh(float lo, float hi) {
    return (u64)__float_as_uint(lo) | ((u64)__float_as_uint(hi) << 32);
}
__device__ __forceinline__ void fma2(u64& d, u64 a, u64 b) {
    asm("fma.rn.f32x2 %0, %1, %2, %0;" : "+l"(d) : "l"(a), "l"(b));
}
__device__ __forceinline__ u64 add2(u64 a, u64 b) {
    u64 d;
    asm("add.rn.f32x2 %0, %1, %2;" : "=l"(d) : "l"(a), "l"(b));
    return d;
}
__device__ __forceinline__ float ex2(float x) {
    float y; asm("ex2.approx.f32 %0, %1;" : "=f"(y) : "f"(x)); return y;
}
__device__ __forceinline__ float lg2(float x) {
    float y; asm("lg2.approx.f32 %0, %1;" : "=f"(y) : "f"(x)); return y;
}
__device__ __forceinline__ int ldacq(const int* p) {
    int v;
    asm volatile("ld.acquire.gpu.global.b32 %0, [%1];" : "=r"(v) : "l"(p) : "memory");
    return v;
}
__device__ __forceinline__ void strel(int* p, int v) {
    asm volatile("st.release.gpu.global.b32 [%0], %1;" :: "l"(p), "r"(v) : "memory");
}
__device__ __forceinline__ void bar64() {
    asm volatile("bar.sync 1, 64;" ::: "memory");
}

// ---------------------------------------------------------------------------
// Init: reset flags/counters each graph replay (deterministic).
// ---------------------------------------------------------------------------
__global__ void __launch_bounds__(256) init_kernel() {
    const int t = threadIdx.x;
    for (int i = t; i < NTILES; i += 256) g_flags[i] = 0;
    if (t == 0) { g_ctr = 0; g_done = 0; }
}

// ---------------------------------------------------------------------------
// Fused kernel: 296 CTAs x 256 threads.
//   bid <  168 : persistent GEMM worker — work-steals 128-row tiles in
//                s-major order (tau = s_tile*128 + batch), tf32 mma.sync,
//                3-stage cp.async pipeline, publishes per-tile flag.
//   bid >= 168 : CRF scan for batch b = bid-168 (2 warps active), waits on
//                tile flags at tranche boundaries; gold score fused; the
//                last scan CTA reduces the loss.
// ---------------------------------------------------------------------------
__global__ void __launch_bounds__(256, 2) fused_kernel(
    const float* __restrict__ A,     // [B*S, D]
    const float* __restrict__ W,     // [50, D]
    const float* __restrict__ bias,  // [50]
    const float* __restrict__ T,     // [52,52]
    const int*   __restrict__ lens,  // [B]
    const int*   __restrict__ labels,// [B,S]
    float* __restrict__ out)
{
    extern __shared__ __align__(16) float smem[];
    __shared__ int s_tau;
    __shared__ __align__(16) float es[2][64];
    __shared__ float redm[2], reds[2];
    __shared__ int s_last;
    __shared__ float sred[8];

    const int bid  = blockIdx.x;
    const int tid  = threadIdx.x;
    const int w    = tid >> 5;
    const int lane = tid & 31;

    if (bid < GEMM_CTAS) {
        // ================= GEMM worker =================
        const int gr = lane >> 2;        // groupID
        const int tg = lane & 3;         // thread-in-group
        const unsigned sb = smem_u32(smem);

        for (;;) {
            __syncthreads();
            if (tid == 0) s_tau = atomicAdd(&g_ctr, 1);
            __syncthreads();
            const int tau = s_tau;
            if (tau >= NTILES) break;

            const int tr = tau >> 7;          // s-tile 0..3
            const int b  = tau & 127;         // batch
            const int st = tr * 128;
            const int len = lens[b];

            if (st < len) {
                const int row0 = b * Sn + st;
                const int maxrow = min(128, len - st);

                float acc[8][4];
#pragma unroll
                for (int q = 0; q < 8; q++)
#pragma unroll
                    for (int r = 0; r < 4; r++) acc[q][r] = 0.f;

                auto stage = [&](int c) {
                    const int kc = c * KCH;
                    const int buf = c % 3;
                    const unsigned ab = sb + (unsigned)(buf * AS1) * 4;
                    const unsigned bb = sb + (unsigned)(3 * AS1 + buf * BS1) * 4;
#pragma unroll
                    for (int i = 0; i < 4; i++) {
                        int slot = tid + i * 256;          // 0..1023
                        int row = slot >> 3, j = slot & 7;
                        if (row < maxrow)
                            cp16(ab + (unsigned)(row * KP + 4 * j) * 4,
                                 A + (size_t)(row0 + row) * Dk + kc + 4 * j);
                    }
#pragma unroll
                    for (int i = 0; i < 2; i++) {
                        int slot = tid + i * 256;          // 0..511
                        int row = slot >> 3, j = slot & 7;
                        if (row < Ln)
                            cp16(bb + (unsigned)(row * KP + 4 * j) * 4,
                                 W + (size_t)row * Dk + kc + 4 * j);
                    }
                    cp_commit();
                };

                stage(0); stage(1); stage(2);

                for (int c = 0; c < NCHK; c++) {
                    if (c <= NCHK - 3)      cp_wait<2>();
                    else if (c == NCHK - 2) cp_wait<1>();
                    else                    cp_wait<0>();
                    __syncthreads();

                    const int buf = c % 3;
                    const float* Ab = smem + buf * AS1 + (16 * w + gr) * KP;
                    const float* Bb = smem + 3 * AS1 + buf * BS1 + gr * KP;
#pragma unroll
                    for (int s = 0; s < 4; s++) {
                        const int k = 8 * s + tg;
                        unsigned a[4];
                        a[0] = __float_as_uint(Ab[k]);
                        a[1] = __float_as_uint(Ab[8 * KP + k]);
                        a[2] = __float_as_uint(Ab[k + 4]);
                        a[3] = __float_as_uint(Ab[8 * KP + k + 4]);
#pragma unroll
                        for (int q = 0; q < 8; q++) {
                            unsigned b0 = __float_as_uint(Bb[8 * q * KP + k]);
                            unsigned b1 = __float_as_uint(Bb[8 * q * KP + k + 4]);
                            mma_tf32(acc[q], a, b0, b1);
                        }
                    }
                    __syncthreads();
                    if (c + 3 < NCHK) stage(c + 3);
                }

                // epilogue: + bias, float2 stores
#pragma unroll
                for (int q = 0; q < 8; q++) {
                    const int n = 8 * q + 2 * tg;
                    if (n < 49) {
                        const float b0v = bias[n], b1v = bias[n + 1];
                        const int rg = row0 + 16 * w + gr;
                        float2 v0 = make_float2(acc[q][0] + b0v, acc[q][1] + b1v);
                        float2 v1 = make_float2(acc[q][2] + b0v, acc[q][3] + b1v);
                        *reinterpret_cast<float2*>(g_logits + (size_t)rg * Ln + n) = v0;
                        *reinterpret_cast<float2*>(g_logits + (size_t)(rg + 8) * Ln + n) = v1;
                    }
                }
            }

            __syncthreads();
            if (tid == 0) { __threadfence(); strel(&g_flags[tau], 1); }
        }
        return;
    }

    // ================= scan CTA =================
    const int b = bid - GEMM_CTAS;          // batch
    const int len = lens[b];
    const float* lg = g_logits + (size_t)b * Sn * Ln;

    float norm_val = 0.f;                   // tid 0 only

    if (tid < 64) {
        const int i = w * 26 + lane;        // destination label
        const bool valid    = (lane < 26);
        const bool hasLogit = valid && (i < Ln);
        const float* Trow = T + (valid ? i : 0) * NL;

        // packed exp(transition) row: 26 u64 = 52 regs
        u64 eTp[26];
#pragma unroll
        for (int q = 0; q < 26; q++) {
            float e0 = valid ? __expf(Trow[2 * q])     : 0.f;
            float e1 = valid ? __expf(Trow[2 * q + 1]) : 0.f;
            eTp[q] = packlh(e0, e1);
        }

        auto wait_tile = [&](int tr) {
            const int* f = &g_flags[tr * 128 + b];
            if (!ldacq(f)) { while (!ldacq(f)) __nanosleep(200); }
        };

        wait_tile(0);

        // base-2 domain: r2 = alpha * log2(e); logits scaled at load.
        float r2 = valid ? (Trow[STARTL] + (hasLogit ? lg[i] : NEGV)) * LOG2E
                         : -1e30f;
        float off2 = 0.f, c2 = 0.f;

        // logit prefetch ring, depth 4
        float p0 = 0.f, p1 = 0.f, p2 = 0.f, p3 = 0.f;
        if (1 < len) p0 = (hasLogit ? lg[Ln + i]     : NEGV) * LOG2E;
        if (2 < len) p1 = (hasLogit ? lg[2 * Ln + i] : NEGV) * LOG2E;
        if (3 < len) p2 = (hasLogit ? lg[3 * Ln + i] : NEGV) * LOG2E;
        if (4 < len) p3 = (hasLogit ? lg[4 * Ln + i] : NEGV) * LOG2E;

        for (int t = 1; t < len; t++) {
            const float u = ex2(r2 - c2);
            if (valid) es[t & 1][i] = u;
            bar64();
            const float* eb = es[t & 1];

            u64 a0 = 0ull, a1 = 0ull, a2 = 0ull, a3 = 0ull;
            float u0 = 0.f;
#pragma unroll
            for (int q = 0; q < 13; q++) {
                ulonglong2 ev = *reinterpret_cast<const ulonglong2*>(&eb[4 * q]);
                if (q == 0) u0 = __uint_as_float((unsigned)ev.x);
                if (q & 1) { fma2(a0, eTp[2 * q], ev.x); fma2(a1, eTp[2 * q + 1], ev.y); }
                else       { fma2(a2, eTp[2 * q], ev.x); fma2(a3, eTp[2 * q + 1], ev.y); }
            }
            u64 tot = add2(add2(a0, a1), add2(a2, a3));
            float s = __uint_as_float((unsigned)tot) +
                      __uint_as_float((unsigned)(tot >> 32));

            r2 = lg2(s) + p0;               // dead lanes: lg2(0) = -inf
            const float cold = c2;
            off2 += cold;
            c2 = lg2(u0) + cold;            // stale-by-one renorm constant

            p0 = p1; p1 = p2; p2 = p3;
            const int tn = t + 4;
            if (tn < len) {
                if ((tn & 127) == 0) wait_tile(tn >> 7);
                p3 = (hasLogit ? lg[tn * Ln + i] : NEGV) * LOG2E;
            }
        }

        // norm = ln2 * (off2 + LSE2_i(r2_i + T[END][i]*log2e))
        float v2 = valid ? (r2 + T[ENDL * NL + i] * LOG2E) : -1e30f;
        float m2 = v2;
#pragma unroll
        for (int o = 16; o; o >>= 1) m2 = fmaxf(m2, __shfl_xor_sync(FULL, m2, o));
        if (lane == 0) redm[w] = m2;
        bar64();
        m2 = fmaxf(redm[0], redm[1]);
        float sx = (valid && v2 > -1e29f) ? ex2(v2 - m2) : 0.f;
#pragma unroll
        for (int o = 16; o; o >>= 1) sx += __shfl_xor_sync(FULL, sx, o);
        if (lane == 0) reds[w] = sx;
        bar64();
        if (tid == 0) norm_val = LN2 * (off2 + m2 + lg2(reds[0] + reds[1]));

        // ---- gold score (natural domain) ----
        const int* lab = labels + b * Sn;
        float gs = 0.f;
        for (int t = tid; t < len; t += 64) {
            int lt = lab[t];
            int prev = (t == 0) ? STARTL : lab[t - 1];
            gs += lg[t * Ln + lt] + T[lt * NL + prev];
        }
        if (tid == 0) gs += T[ENDL * NL + lab[len - 1]];
#pragma unroll
        for (int o = 16; o; o >>= 1) gs += __shfl_xor_sync(FULL, gs, o);
        bar64();                             // redm reuse safety
        if (lane == 0) redm[w] = gs;
        bar64();
        if (tid == 0) g_partial[b] = (redm[0] + redm[1]) - norm_val;
    }

    // ---- last scan CTA reduces the loss ----
    __syncthreads();
    if (tid == 0) {
        __threadfence();
        int old = atomicAdd(&g_done, 1);
        s_last = (old == Bn - 1);
    }
    __syncthreads();
    if (s_last) {
        __threadfence();
        float v = (tid < Bn) ? g_partial[tid] : 0.f;
#pragma unroll
        for (int o = 16; o; o >>= 1) v += __shfl_xor_sync(FULL, v, o);
        if (lane == 0) sred[w] = v;
        __syncthreads();
        if (tid == 0) {
            float tot = 0.f;
#pragma unroll
            for (int k = 0; k < 8; k++) tot += sred[k];
            out[0] = -tot;
        }
    }
}

// ---------------------------------------------------------------------------
extern "C" void kernel_launch(void* const* d_in, const int* in_sizes, int n_in,
                              void* d_out, int out_size)
{
    const float* inputs  = (const float*)d_in[0];   // [128,512,1024]
    const float* W       = (const float*)d_in[1];   // [50,1024]
    const float* bias    = (const float*)d_in[2];   // [50]
    const float* T       = (const float*)d_in[3];   // [52,52]
    const int*   lens    = (const int*)  d_in[4];   // [128]
    const int*   labels  = (const int*)  d_in[5];   // [128,512]
    float* out = (float*)d_out;

    static bool attr_set = false;
    if (!attr_set) {
        cudaFuncSetAttribute(fused_kernel,
                             cudaFuncAttributeMaxDynamicSharedMemorySize,
                             SMEM_BYTES);
        attr_set = true;
    }

    init_kernel<<<1, 256>>>();
    fused_kernel<<<GEMM_CTAS + Bn, 256, SMEM_BYTES>>>(
        inputs, W, bias, T, lens, labels, out);
}

// round 13
// speedup vs baseline: 1.2021x; 1.2021x over previous
#include <cuda_runtime.h>
#include <cstdint>

#define FULL 0xffffffffu
typedef unsigned long long u64;

constexpr int Bn = 128;      // batch
constexpr int Sn = 512;      // seq len
constexpr int Dk = 1024;     // feature dim
constexpr int Ln = 50;       // real labels
constexpr int NL = 52;       // labels + START + END
constexpr int STARTL = 50;
constexpr int ENDL = 51;
constexpr float NEGV = -100.0f;
constexpr float LOG2E = 1.4426950408889634f;
constexpr float LN2   = 0.6931471805599453f;

// ---- mma.sync GEMM config (R11, measured 70us) ----
constexpr int TM  = 256;           // rows per CTA
constexpr int KCH = 32;            // k per chunk
constexpr int NCH = Dk / KCH;      // 32 chunks
constexpr int KP  = 36;            // padded k stride (floats)
constexpr int ASZ = TM * KP;       // floats per A buffer (9216)
constexpr int BSZ = 64 * KP;       // floats per B buffer (2304)
constexpr int SMEM_BYTES = (2 * ASZ + 2 * BSZ) * 4;   // 92160

// Scratch (device globals — no allocation allowed)
__device__ float g_logits[(size_t)Bn * Sn * Ln];   // 13.1 MB
__device__ float g_partial[Bn];

// ---------------- PTX helpers ----------------
__device__ __forceinline__ unsigned smem_u32(const void* p) {
    unsigned a;
    asm("{ .reg .u64 t; cvta.to.shared.u64 t, %1; cvt.u32.u64 %0, t; }"
        : "=r"(a) : "l"(p));
    return a;
}
__device__ __forceinline__ void cp16(unsigned dst, const void* src) {
    asm volatile("cp.async.cg.shared.global [%0], [%1], 16;"
                 :: "r"(dst), "l"(src) : "memory");
}
__device__ __forceinline__ void cp_commit() {
    asm volatile("cp.async.commit_group;" ::: "memory");
}
template <int N>
__device__ __forceinline__ void cp_wait() {
    asm volatile("cp.async.wait_group %0;" :: "n"(N) : "memory");
}
__device__ __forceinline__ void mma_tf32(float* c, const unsigned* a,
                                         unsigned b0, unsigned b1) {
    asm volatile(
        "mma.sync.aligned.m16n8k8.row.col.f32.tf32.tf32.f32 "
        "{%0,%1,%2,%3}, {%4,%5,%6,%7}, {%8,%9}, {%0,%1,%2,%3};"
        : "+f"(c[0]), "+f"(c[1]), "+f"(c[2]), "+f"(c[3])
        : "r"(a[0]), "r"(a[1]), "r"(a[2]), "r"(a[3]), "r"(b0), "r"(b1));
}
__device__ __forceinline__ u64 packlh(float lo, float hi) {
    return (u64)__float_as_uint(lo) | ((u64)__float_as_uint(hi) << 32);
}
__device__ __forceinline__ void fma2(u64& d, u64 a, u64 b) {
    asm("fma.rn.f32x2 %0, %1, %2, %0;" : "+l"(d) : "l"(a), "l"(b));
}
__device__ __forceinline__ u64 add2(u64 a, u64 b) {
    u64 d;
    asm("add.rn.f32x2 %0, %1, %2;" : "=l"(d) : "l"(a), "l"(b));
    return d;
}
__device__ __forceinline__ float ex2(float x) {
    float y; asm("ex2.approx.f32 %0, %1;" : "=f"(y) : "f"(x)); return y;
}
__device__ __forceinline__ float lg2(float x) {
    float y; asm("lg2.approx.f32 %0, %1;" : "=f"(y) : "f"(x)); return y;
}

// ---------------------------------------------------------------------------
// Kernel 1: logits = inputs @ W^T + b  via tf32 mma.sync (m16n8k8).
// 256 threads, 256-row x 64-col tile, cp.async double-buffered K chunks.
// (unchanged from R11: measured 70us, tensor 27%, DRAM 24%)
// ---------------------------------------------------------------------------
__global__ void __launch_bounds__(256, 2) gemm_kernel(
    const float* __restrict__ A,     // [B*S, D]
    const float* __restrict__ W,     // [50, D]
    const float* __restrict__ bias,  // [50]
    const int*   __restrict__ lens)  // [B]
{
    extern __shared__ __align__(16) float smem[];
    float* As = smem;                // [2][TM][KP]
    float* Bs = smem + 2 * ASZ;      // [2][64][KP]

    const int blk = blockIdx.x;          // 0..255
    const int bb  = blk >> 1;            // batch
    const int st  = (blk & 1) << 8;      // s-tile start (0 or 256)
    const int len = lens[bb];
    if (st >= len) return;               // fully-masked tile
    const int maxrow = len - st;

    const int tid  = threadIdx.x;
    const int w    = tid >> 5;
    const int lane = tid & 31;
    const int gr   = lane >> 2;          // groupID
    const int tg   = lane & 3;           // thread-in-group
    const int row0 = bb * Sn + st;

    const unsigned sbase = smem_u32(smem);
    const unsigned aoff[2] = {sbase, sbase + ASZ * 4};
    const unsigned boff[2] = {sbase + 2 * ASZ * 4, sbase + 2 * ASZ * 4 + BSZ * 4};

    auto stage = [&](int c) {
        const int kc = c * KCH;
        const int buf = c & 1;
#pragma unroll
        for (int i = 0; i < 8; i++) {
            int slot = tid + i * 256;        // 0..2047
            int row = slot >> 3, j = slot & 7;
            if (row < maxrow)
                cp16(aoff[buf] + (unsigned)(row * KP + 4 * j) * 4,
                     A + (size_t)(row0 + row) * Dk + kc + 4 * j);
        }
#pragma unroll
        for (int i = 0; i < 2; i++) {
            int slot = tid + i * 256;        // 0..511
            int row = slot >> 3, j = slot & 7;
            if (row < Ln)
                cp16(boff[buf] + (unsigned)(row * KP + 4 * j) * 4,
                     W + (size_t)row * Dk + kc + 4 * j);
        }
        cp_commit();
    };

    float acc[2][8][4];
#pragma unroll
    for (int p = 0; p < 2; p++)
#pragma unroll
        for (int q = 0; q < 8; q++)
#pragma unroll
            for (int r = 0; r < 4; r++) acc[p][q][r] = 0.f;

    stage(0);
    stage(1);

    for (int c = 0; c < NCH; c++) {
        if (c + 1 < NCH) cp_wait<1>(); else cp_wait<0>();
        __syncthreads();

        const int buf = c & 1;
        const float* Ab = As + buf * ASZ + (32 * w + gr) * KP;
        const float* Bb = Bs + buf * BSZ + gr * KP;
#pragma unroll
        for (int s = 0; s < 4; s++) {
            const int k = 8 * s + tg;
            unsigned a[2][4];
#pragma unroll
            for (int p = 0; p < 2; p++) {
                const float* ap = Ab + 16 * p * KP;
                a[p][0] = __float_as_uint(ap[k]);
                a[p][1] = __float_as_uint(ap[8 * KP + k]);
                a[p][2] = __float_as_uint(ap[k + 4]);
                a[p][3] = __float_as_uint(ap[8 * KP + k + 4]);
            }
#pragma unroll
            for (int q = 0; q < 8; q++) {
                unsigned b0 = __float_as_uint(Bb[8 * q * KP + k]);
                unsigned b1 = __float_as_uint(Bb[8 * q * KP + k + 4]);
                mma_tf32(acc[0][q], a[0], b0, b1);
                mma_tf32(acc[1][q], a[1], b0, b1);
            }
        }
        __syncthreads();
        if (c + 2 < NCH) stage(c + 2);
    }

    // ---- epilogue: + bias, direct float2 stores ----
#pragma unroll
    for (int q = 0; q < 8; q++) {
        const int n = 8 * q + 2 * tg;
        if (n < 49) {
            const float b0v = bias[n], b1v = bias[n + 1];
#pragma unroll
            for (int p = 0; p < 2; p++) {
                const int rg = row0 + 32 * w + 16 * p + gr;
                float2 v0 = make_float2(acc[p][q][0] + b0v, acc[p][q][1] + b1v);
                float2 v1 = make_float2(acc[p][q][2] + b0v, acc[p][q][3] + b1v);
                *reinterpret_cast<float2*>(g_logits + (size_t)rg * Ln + n) = v0;
                *reinterpret_cast<float2*>(g_logits + (size_t)(rg + 8) * Ln + n) = v1;
            }
        }
    }
}

// ---------------------------------------------------------------------------
// Kernel 2: CRF forward scan + gold, one 64-thread block per batch
// (128 CTAs -> one per SM, no co-residency). Base-2 domain, depth-4 logit
// prefetch ring, one __syncthreads per step, stale-by-one renorm constant.
// ---------------------------------------------------------------------------
__global__ void __launch_bounds__(64) scan_kernel(
    const float* __restrict__ T,      // [52,52], T[i][j] = trans to i from j
    const int*   __restrict__ lens,
    const int*   __restrict__ labels)
{
    __shared__ __align__(16) float es[2][64];
    __shared__ float redm[2], reds[2];
    __shared__ float snorm;

    const int b    = blockIdx.x;
    const int tid  = threadIdx.x;            // 0..63
    const int warp = tid >> 5;
    const int lane = tid & 31;
    const int i    = warp * 26 + lane;       // destination label
    const bool valid    = (lane < 26);
    const bool hasLogit = valid && (i < Ln);
    const int len = lens[b];
    const float* lg = g_logits + (size_t)b * Sn * Ln;
    const float* Trow = T + (valid ? i : 0) * NL;

    // packed exp(transition) row: 26 u64 = 52 regs
    u64 eTp[26];
#pragma unroll
    for (int q = 0; q < 26; q++) {
        float e0 = valid ? __expf(Trow[2 * q])     : 0.f;
        float e1 = valid ? __expf(Trow[2 * q + 1]) : 0.f;
        eTp[q] = packlh(e0, e1);
    }

    // base-2 domain: r2 = alpha * log2(e)
    float r2 = valid ? (Trow[STARTL] + (hasLogit ? lg[i] : NEGV)) * LOG2E
                     : -1e30f;
    float off2 = 0.f, c2 = 0.f;

    // logit prefetch ring, depth 4
    float p0 = 0.f, p1 = 0.f, p2 = 0.f, p3 = 0.f;
    if (1 < len) p0 = (hasLogit ? lg[Ln + i]     : NEGV) * LOG2E;
    if (2 < len) p1 = (hasLogit ? lg[2 * Ln + i] : NEGV) * LOG2E;
    if (3 < len) p2 = (hasLogit ? lg[3 * Ln + i] : NEGV) * LOG2E;
    if (4 < len) p3 = (hasLogit ? lg[4 * Ln + i] : NEGV) * LOG2E;

    for (int t = 1; t < len; t++) {
        const float u = ex2(r2 - c2);
        if (valid) es[t & 1][i] = u;
        __syncthreads();
        const float* eb = es[t & 1];

        u64 a0 = 0ull, a1 = 0ull, a2 = 0ull, a3 = 0ull;
        float u0 = 0.f;
#pragma unroll
        for (int q = 0; q < 13; q++) {
            ulonglong2 ev = *reinterpret_cast<const ulonglong2*>(&eb[4 * q]);
            if (q == 0) u0 = __uint_as_float((unsigned)ev.x);
            if (q & 1) { fma2(a0, eTp[2 * q], ev.x); fma2(a1, eTp[2 * q + 1], ev.y); }
            else       { fma2(a2, eTp[2 * q], ev.x); fma2(a3, eTp[2 * q + 1], ev.y); }
        }
        u64 tot = add2(add2(a0, a1), add2(a2, a3));
        float s = __uint_as_float((unsigned)tot) +
                  __uint_as_float((unsigned)(tot >> 32));

        r2 = lg2(s) + p0;                   // dead lanes: lg2(0) = -inf
        const float cold = c2;
        off2 += cold;
        c2 = lg2(u0) + cold;                // stale-by-one renorm constant

        p0 = p1; p1 = p2; p2 = p3;
        const int tn = t + 4;
        if (tn < len) p3 = (hasLogit ? lg[tn * Ln + i] : NEGV) * LOG2E;
    }

    // norm = ln2 * (off2 + LSE2_i(r2_i + T[END][i]*log2e))
    float v2 = valid ? (r2 + T[ENDL * NL + i] * LOG2E) : -1e30f;
    float m2 = v2;
#pragma unroll
    for (int o = 16; o; o >>= 1) m2 = fmaxf(m2, __shfl_xor_sync(FULL, m2, o));
    if (lane == 0) redm[warp] = m2;
    __syncthreads();
    m2 = fmaxf(redm[0], redm[1]);
    float sx = (valid && v2 > -1e29f) ? ex2(v2 - m2) : 0.f;
#pragma unroll
    for (int o = 16; o; o >>= 1) sx += __shfl_xor_sync(FULL, sx, o);
    if (lane == 0) reds[warp] = sx;
    __syncthreads();
    if (tid == 0) snorm = LN2 * (off2 + m2 + lg2(reds[0] + reds[1]));

    // ---- gold score (natural domain) ----
    const int* lab = labels + b * Sn;
    float gs = 0.f;
    for (int t = tid; t < len; t += 64) {
        int lt = lab[t];
        int prev = (t == 0) ? STARTL : lab[t - 1];
        gs += lg[t * Ln + lt] + T[lt * NL + prev];
    }
    if (tid == 0) gs += T[ENDL * NL + lab[len - 1]];
#pragma unroll
    for (int o = 16; o; o >>= 1) gs += __shfl_xor_sync(FULL, gs, o);
    __syncthreads();
    if (lane == 0) redm[warp] = gs;
    __syncthreads();
    if (tid == 0) g_partial[b] = (redm[0] + redm[1]) - snorm;
}

// ---------------------------------------------------------------------------
// Kernel 3: loss = -sum_b partial[b]
// ---------------------------------------------------------------------------
__global__ void __launch_bounds__(128) finalize_kernel(float* __restrict__ out)
{
    const int tid = threadIdx.x;
    float v = g_partial[tid];
#pragma unroll
    for (int o = 16; o; o >>= 1) v += __shfl_xor_sync(FULL, v, o);
    __shared__ float red[4];
    if ((tid & 31) == 0) red[tid >> 5] = v;
    __syncthreads();
    if (tid == 0) {
        out[0] = -((red[0] + red[1]) + (red[2] + red[3]));
    }
}

// ---------------------------------------------------------------------------
extern "C" void kernel_launch(void* const* d_in, const int* in_sizes, int n_in,
                              void* d_out, int out_size)
{
    const float* inputs  = (const float*)d_in[0];   // [128,512,1024]
    const float* W       = (const float*)d_in[1];   // [50,1024]
    const float* bias    = (const float*)d_in[2];   // [50]
    const float* T       = (const float*)d_in[3];   // [52,52]
    const int*   lens    = (const int*)  d_in[4];   // [128]
    const int*   labels  = (const int*)  d_in[5];   // [128,512]
    float* out = (float*)d_out;

    static bool attr_set = false;
    if (!attr_set) {
        cudaFuncSetAttribute(gemm_kernel,
                             cudaFuncAttributeMaxDynamicSharedMemorySize,
                             SMEM_BYTES);
        attr_set = true;
    }

    gemm_kernel<<<Bn * (Sn / TM), 256, SMEM_BYTES>>>(inputs, W, bias, lens);
    scan_kernel<<<Bn, 64>>>(T, lens, labels);
    finalize_kernel<<<1, 128>>>(out);
}